// round 15
// baseline (speedup 1.0000x reference)
#include <cuda_runtime.h>
#include <math.h>

// Problem constants (fixed by setup_inputs): B=2, N=6890, NF=2000
#define B_    2
#define NMAX  7168
#define NFMAX 2048
#define WCH   16       // triangle chunks for winding  (7*4*16 = 448 blocks ~ one wave @3/SM)
#define WFPC  125      // max tris per chunk staged in smem (ceil(2000/16)=125)
#define MCH   21       // point chunks for minsq       (7*4*21 = 588 blocks)
#define NB1   32       // stage-1 reduce blocks per segment
#define NTC   19       // triangle components (law-of-cosines form)
#define BIGF  3.4e38f

typedef unsigned long long ull;

// -------- device scratch (no allocations allowed) --------
__device__ float4 g_pts4[2][B_ * NMAX];            // (x,y,z,|p|^2)
// triangles SoA: [src][ (b*NTC + comp)*NFMAX + f ]
// comps: 0-2 2A, 3 |A|^2, 4-6 2B, 7 |B|^2, 8-10 2C, 11 |C|^2,
//        12-14 n=(B-A)x(C-A), 15 d0=A.n,
//        16 -|A-B|^2, 17 -|B-C|^2, 18 -|C-A|^2
__device__ float g_triS[2][B_ * NTC * NFMAX];
__device__ float g_wpart[WCH][4 * NMAX];           // partial atan2 sums
__device__ float g_mpart[MCH][4 * NMAX];           // partial sq-dist mins
__device__ float4 g_red[4][NB1];                   // (mn, mx, sum, cnt)

// ---------------- packed f32x2 helpers (sm_100+) ----------------
__device__ __forceinline__ ull pk2(float lo, float hi) {
    ull r;
    asm("mov.b64 %0, {%1, %2};" : "=l"(r)
        : "r"(__float_as_uint(lo)), "r"(__float_as_uint(hi)));
    return r;
}
__device__ __forceinline__ float2 unpk2(ull v) {
    unsigned int lo, hi;
    asm("mov.b64 {%0, %1}, %2;" : "=r"(lo), "=r"(hi) : "l"(v));
    return make_float2(__uint_as_float(lo), __uint_as_float(hi));
}
__device__ __forceinline__ ull fma2(ull a, ull b, ull c) {
    ull d; asm("fma.rn.f32x2 %0, %1, %2, %3;" : "=l"(d) : "l"(a), "l"(b), "l"(c)); return d;
}
__device__ __forceinline__ ull add2(ull a, ull b) {
    ull d; asm("add.rn.f32x2 %0, %1, %2;" : "=l"(d) : "l"(a), "l"(b)); return d;
}
__device__ __forceinline__ ull mul2(ull a, ull b) {
    ull d; asm("mul.rn.f32x2 %0, %1, %2;" : "=l"(d) : "l"(a), "l"(b)); return d;
}
__device__ __forceinline__ float sqrt_ap(float x) {
    float r; asm("sqrt.approx.f32 %0, %1;" : "=f"(r) : "f"(x)); return r;
}

// ---------------------------------------------------------
// gather A: float4 points (with |p|^2)
// ---------------------------------------------------------
__global__ void gather_pts_kernel(const float* __restrict__ v1,
                                  const float* __restrict__ v2,
                                  int N) {
    int stride = gridDim.x * blockDim.x;
    int t0 = blockIdx.x * blockDim.x + threadIdx.x;
    int PT = B_ * N;
    for (int i = t0; i < PT; i += stride) {
        float x = v1[i * 3 + 0], y = v1[i * 3 + 1], z = v1[i * 3 + 2];
        g_pts4[0][i] = make_float4(x, y, z, fmaf(x, x, fmaf(y, y, z * z)));
        x = v2[i * 3 + 0]; y = v2[i * 3 + 1]; z = v2[i * 3 + 2];
        g_pts4[1][i] = make_float4(x, y, z, fmaf(x, x, fmaf(y, y, z * z)));
    }
}

// ---------------------------------------------------------
// gather B: triangle SoA (law-of-cosines form)
// ---------------------------------------------------------
__global__ void gather_tri_kernel(const float* __restrict__ v1,
                                  const float* __restrict__ v2,
                                  const int*   __restrict__ faces,
                                  int N, int NF) {
    int stride = gridDim.x * blockDim.x;
    int t0 = blockIdx.x * blockDim.x + threadIdx.x;
    int FT = B_ * NF;
    for (int i = t0; i < FT; i += stride) {
        int b = i / NF;
        int f = i - b * NF;
        int i0 = faces[f * 3 + 0];
        int i1 = faces[f * 3 + 1];
        int i2 = faces[f * 3 + 2];
        int base = b * N * 3;
        #pragma unroll
        for (int s = 0; s < 2; s++) {
            const float* v = (s == 0) ? v1 : v2;
            float Ax = v[base + i0 * 3 + 0], Ay = v[base + i0 * 3 + 1], Az = v[base + i0 * 3 + 2];
            float Bx = v[base + i1 * 3 + 0], By = v[base + i1 * 3 + 1], Bz = v[base + i1 * 3 + 2];
            float Cx = v[base + i2 * 3 + 0], Cy = v[base + i2 * 3 + 1], Cz = v[base + i2 * 3 + 2];
            float ex = Bx - Ax, ey = By - Ay, ez = Bz - Az;
            float fx = Cx - Ax, fy = Cy - Ay, fz = Cz - Az;
            float gx = Cx - Bx, gy = Cy - By, gz = Cz - Bz;
            float nx = fmaf(ey, fz, -ez * fy);
            float ny = fmaf(ez, fx, -ex * fz);
            float nz = fmaf(ex, fy, -ey * fx);
            float d0 = fmaf(Ax, nx, fmaf(Ay, ny, Az * nz));
            float A2 = fmaf(Ax, Ax, fmaf(Ay, Ay, Az * Az));
            float B2 = fmaf(Bx, Bx, fmaf(By, By, Bz * Bz));
            float C2 = fmaf(Cx, Cx, fmaf(Cy, Cy, Cz * Cz));
            float Lab = fmaf(ex, ex, fmaf(ey, ey, ez * ez));   // |A-B|^2
            float Lbc = fmaf(gx, gx, fmaf(gy, gy, gz * gz));   // |B-C|^2
            float Lca = fmaf(fx, fx, fmaf(fy, fy, fz * fz));   // |C-A|^2
            float* T = g_triS[s] + (size_t)(b * NTC) * NFMAX + f;
            T[0 * NFMAX] = 2.0f * Ax;  T[1 * NFMAX] = 2.0f * Ay;  T[2 * NFMAX] = 2.0f * Az;
            T[3 * NFMAX] = A2;
            T[4 * NFMAX] = 2.0f * Bx;  T[5 * NFMAX] = 2.0f * By;  T[6 * NFMAX] = 2.0f * Bz;
            T[7 * NFMAX] = B2;
            T[8 * NFMAX] = 2.0f * Cx;  T[9 * NFMAX] = 2.0f * Cy;  T[10 * NFMAX] = 2.0f * Cz;
            T[11 * NFMAX] = C2;
            T[12 * NFMAX] = nx;  T[13 * NFMAX] = ny;  T[14 * NFMAX] = nz;
            T[15 * NFMAX] = d0;
            T[16 * NFMAX] = -Lab;  T[17 * NFMAX] = -Lbc;  T[18 * NFMAX] = -Lca;
        }
    }
}

// ---------------------------------------------------------
// minsq: 4 scalar points per thread vs packed pairs of q.
// grid: x covers Q=ceil(N/4), y = seg*MCH + chunk (seg = dir*2+b)
// ---------------------------------------------------------
__global__ void __launch_bounds__(256)
minsq_kernel(int N) {
    int yc = blockIdx.y;
    int seg = yc / MCH;
    int chunk = yc - seg * MCH;
    int dir = seg >> 1;
    int b = seg & 1;
    int Q = (N + 3) >> 2;
    int t = blockIdx.x * 256 + threadIdx.x;
    if (t >= Q) return;

    const float4* __restrict__ P = g_pts4[dir] + b * N;
    const float4* __restrict__ O = g_pts4[1 - dir] + b * N;

    int i0 = t, i1 = t + Q, i2 = t + 2 * Q, i3 = t + 3 * Q;
    bool ok3 = (i3 < N);
    float4 p0 = P[i0];
    float4 p1 = P[i1];
    float4 p2 = P[i2];
    float4 p3 = ok3 ? P[i3] : p2;

    ull p0x = pk2(p0.x, p0.x), p0y = pk2(p0.y, p0.y), p0z = pk2(p0.z, p0.z);
    ull p1x = pk2(p1.x, p1.x), p1y = pk2(p1.y, p1.y), p1z = pk2(p1.z, p1.z);
    ull p2x = pk2(p2.x, p2.x), p2y = pk2(p2.y, p2.y), p2z = pk2(p2.z, p2.z);
    ull p3x = pk2(p3.x, p3.x), p3y = pk2(p3.y, p3.y), p3z = pk2(p3.z, p3.z);
    ull m2  = pk2(-2.0f, -2.0f);

    int mpc = (N + MCH - 1) / MCH;
    int m0 = chunk * mpc;
    int m1 = min(N, m0 + mpc);

    float b0 = BIGF, b1v = BIGF, b2v = BIGF, b3v = BIGF;
    int m = m0;
    for (; m + 1 < m1; m += 2) {
        float4 qa = O[m];
        float4 qb = O[m + 1];
        ull qx = pk2(qa.x, qb.x);
        ull qy = pk2(qa.y, qb.y);
        ull qz = pk2(qa.z, qb.z);
        ull qw = pk2(qa.w, qb.w);

        ull d0 = fma2(p0x, qx, fma2(p0y, qy, mul2(p0z, qz)));
        ull d1 = fma2(p1x, qx, fma2(p1y, qy, mul2(p1z, qz)));
        ull d2 = fma2(p2x, qx, fma2(p2y, qy, mul2(p2z, qz)));
        ull d3 = fma2(p3x, qx, fma2(p3y, qy, mul2(p3z, qz)));
        float2 v0 = unpk2(fma2(m2, d0, qw));
        float2 v1 = unpk2(fma2(m2, d1, qw));
        float2 v2 = unpk2(fma2(m2, d2, qw));
        float2 v3 = unpk2(fma2(m2, d3, qw));
        b0  = fminf(b0,  fminf(v0.x, v0.y));
        b1v = fminf(b1v, fminf(v1.x, v1.y));
        b2v = fminf(b2v, fminf(v2.x, v2.y));
        b3v = fminf(b3v, fminf(v3.x, v3.y));
    }
    for (; m < m1; ++m) {
        float4 q = O[m];
        float d0 = fmaf(p0.x, q.x, fmaf(p0.y, q.y, p0.z * q.z));
        float d1 = fmaf(p1.x, q.x, fmaf(p1.y, q.y, p1.z * q.z));
        float d2 = fmaf(p2.x, q.x, fmaf(p2.y, q.y, p2.z * q.z));
        float d3 = fmaf(p3.x, q.x, fmaf(p3.y, q.y, p3.z * q.z));
        b0  = fminf(b0,  fmaf(-2.0f, d0, q.w));
        b1v = fminf(b1v, fmaf(-2.0f, d1, q.w));
        b2v = fminf(b2v, fmaf(-2.0f, d2, q.w));
        b3v = fminf(b3v, fmaf(-2.0f, d3, q.w));
    }
    int base = seg * NMAX;
    g_mpart[chunk][base + i0] = b0 + p0.w;
    g_mpart[chunk][base + i1] = b1v + p1.w;
    g_mpart[chunk][base + i2] = b2v + p2.w;
    if (ok3) g_mpart[chunk][base + i3] = b3v + p3.w;
}

// ---------------------------------------------------------
// packed solid-angle term via law-of-cosines (no diff vectors):
//   a2 = |p|^2 - 2A.p + |A|^2          (np = -p, t2A = 2A)
//   2*a.b = a2 + b2 - |A-B|^2          (s-terms)
//   atan2(2det, 2den) == atan2(det, den)
// ---------------------------------------------------------
__device__ __forceinline__ void pair_accum(
    ull npx, ull npy, ull npz, ull ppw,
    ull t2Ax, ull t2Ay, ull t2Az, ull tA2,
    ull t2Bx, ull t2By, ull t2Bz, ull tB2,
    ull t2Cx, ull t2Cy, ull t2Cz, ull tC2,
    ull tnx, ull tny, ull tnz, ull td0,
    ull tmLab, ull tmLbc, ull tmLca,
    ull C4, ull C3, ull C2c, ull C1, ull C0, ull CC,
    float& acc0, float& acc1)
{
    ull a2 = add2(fma2(t2Ax, npx, fma2(t2Ay, npy, fma2(t2Az, npz, tA2))), ppw);
    ull b2 = add2(fma2(t2Bx, npx, fma2(t2By, npy, fma2(t2Bz, npz, tB2))), ppw);
    ull c2 = add2(fma2(t2Cx, npx, fma2(t2Cy, npy, fma2(t2Cz, npz, tC2))), ppw);

    ull det = fma2(npx, tnx, fma2(npy, tny, fma2(npz, tnz, td0)));

    ull sab = add2(add2(a2, b2), tmLab);   // 2 a.b
    ull sbc = add2(add2(b2, c2), tmLbc);   // 2 b.c
    ull sca = add2(add2(c2, a2), tmLca);   // 2 c.a

    float2 a2s = unpk2(a2), b2s = unpk2(b2), c2s = unpk2(c2);
    ull la = pk2(sqrt_ap(a2s.x), sqrt_ap(a2s.y));
    ull lb = pk2(sqrt_ap(b2s.x), sqrt_ap(b2s.y));
    ull lc = pk2(sqrt_ap(c2s.x), sqrt_ap(c2s.y));

    // den2 = 2*den = (2 la lb + sab) lc + sbc la + sca lb
    ull lb2v = add2(lb, lb);
    ull den = fma2(fma2(la, lb2v, sab), lc,
              fma2(sbc, la, mul2(sca, lb)));
    ull dt2 = add2(det, det);              // 2*det

    // scalar range reduction
    float2 d = unpk2(dt2), n = unpk2(den);
    float ax0 = fabsf(n.x), ay0 = fabsf(d.x);
    float mx0 = fmaxf(ax0, ay0), mn0 = fminf(ax0, ay0);
    float t0 = __fdividef(mn0, fmaxf(mx0, 1e-37f));
    float ax1 = fabsf(n.y), ay1 = fabsf(d.y);
    float mx1 = fmaxf(ax1, ay1), mn1 = fminf(ax1, ay1);
    float t1 = __fdividef(mn1, fmaxf(mx1, 1e-37f));

    // packed polynomial (6-coeff Horner)
    ull T = pk2(t0, t1);
    ull S = mul2(T, T);
    ull Pp = fma2(S, C4, C3);
    Pp = fma2(S, Pp, C2c);
    Pp = fma2(S, Pp, C1);
    Pp = fma2(S, Pp, C0);
    Pp = fma2(S, Pp, CC);
    float2 r = unpk2(mul2(Pp, T));

    // branch-free quadrant fixups + sign via XOR
    {
        bool qhi  = ay0 > ax0;
        bool qneg = n.x < 0.0f;
        float base = qhi ? 1.57079632679f : 0.0f;
        if (qneg) base = 3.14159265359f - base;
        float rs = (qhi != qneg) ? -r.x : r.x;
        float res = base + rs;
        unsigned int sgn = __float_as_uint(d.x) & 0x80000000u;
        acc0 += __uint_as_float(__float_as_uint(res) ^ sgn);
    }
    {
        bool qhi  = ay1 > ax1;
        bool qneg = n.y < 0.0f;
        float base = qhi ? 1.57079632679f : 0.0f;
        if (qneg) base = 3.14159265359f - base;
        float rs = (qhi != qneg) ? -r.y : r.y;
        float res = base + rs;
        unsigned int sgn = __float_as_uint(d.y) & 0x80000000u;
        acc1 += __uint_as_float(__float_as_uint(res) ^ sgn);
    }
}

// ---------------------------------------------------------
// winding: 4 points per thread as two f32x2 pairs; triangle chunk
// staged in smem as duplicated (v,v) pairs (LDS.64 operands).
// grid: x covers H4=ceil(N/4), y = seg*WCH + chunk (seg = dir*2+b)
// ---------------------------------------------------------
__global__ void __launch_bounds__(256)
winding_kernel(int N, int NF) {
    __shared__ ull smT[NTC][WFPC];

    int yc = blockIdx.y;
    int seg = yc / WCH;
    int chunk = yc - seg * WCH;
    int dir = seg >> 1;
    int b = seg & 1;
    int H4 = (N + 3) >> 2;
    int t = blockIdx.x * 256 + threadIdx.x;

    int src = 1 - dir;
    int fpc = (NF + WCH - 1) / WCH;
    int f0 = chunk * fpc;
    int f1 = min(NF, f0 + fpc);
    int nf = f1 - f0;           // <= WFPC

    // cooperative stage: duplicated-pair layout
    {
        const float* Tb = g_triS[src] + (size_t)(b * NTC) * NFMAX + f0;
        #pragma unroll
        for (int c = 0; c < NTC; c++) {
            for (int j = threadIdx.x; j < nf; j += 256) {
                float v = Tb[c * NFMAX + j];
                smT[c][j] = pk2(v, v);
            }
        }
    }
    __syncthreads();

    if (t >= H4) return;

    const float4* __restrict__ P = g_pts4[dir] + b * N;
    int i0 = t, i1 = t + H4, i2 = t + 2 * H4, i3 = t + 3 * H4;
    bool ok3 = (i3 < N);
    float4 p0 = P[i0];
    float4 p1 = P[i1];
    float4 p2 = P[i2];
    float4 p3 = ok3 ? P[i3] : p2;

    ull nAx = pk2(-p0.x, -p1.x), nAy = pk2(-p0.y, -p1.y), nAz = pk2(-p0.z, -p1.z);
    ull nBx = pk2(-p2.x, -p3.x), nBy = pk2(-p2.y, -p3.y), nBz = pk2(-p2.z, -p3.z);
    ull pwA = pk2(p0.w, p1.w);
    ull pwB = pk2(p2.w, p3.w);

    ull C4 = pk2(-0.01172120f, -0.01172120f);
    ull C3 = pk2( 0.05265332f,  0.05265332f);
    ull C2c = pk2(-0.11643287f, -0.11643287f);
    ull C1 = pk2( 0.19354346f,  0.19354346f);
    ull C0 = pk2(-0.33262347f, -0.33262347f);
    ull CC = pk2( 0.99997726f,  0.99997726f);

    float a0 = 0.0f, a1 = 0.0f, a2c = 0.0f, a3 = 0.0f;
    for (int j = 0; j < nf; ++j) {
        ull t2Ax = smT[0][j],  t2Ay = smT[1][j],  t2Az = smT[2][j],  tA2 = smT[3][j];
        ull t2Bx = smT[4][j],  t2By = smT[5][j],  t2Bz = smT[6][j],  tB2 = smT[7][j];
        ull t2Cx = smT[8][j],  t2Cy = smT[9][j],  t2Cz = smT[10][j], tC2 = smT[11][j];
        ull tnx = smT[12][j],  tny = smT[13][j],  tnz = smT[14][j],  td0 = smT[15][j];
        ull tmLab = smT[16][j], tmLbc = smT[17][j], tmLca = smT[18][j];

        pair_accum(nAx, nAy, nAz, pwA,
                   t2Ax, t2Ay, t2Az, tA2, t2Bx, t2By, t2Bz, tB2,
                   t2Cx, t2Cy, t2Cz, tC2, tnx, tny, tnz, td0,
                   tmLab, tmLbc, tmLca,
                   C4, C3, C2c, C1, C0, CC, a0, a1);
        pair_accum(nBx, nBy, nBz, pwB,
                   t2Ax, t2Ay, t2Az, tA2, t2Bx, t2By, t2Bz, tB2,
                   t2Cx, t2Cy, t2Cz, tC2, tnx, tny, tnz, td0,
                   tmLab, tmLbc, tmLca,
                   C4, C3, C2c, C1, C0, CC, a2c, a3);
    }
    int base = seg * NMAX;
    g_wpart[chunk][base + i0] = a0;
    g_wpart[chunk][base + i1] = a1;
    g_wpart[chunk][base + i2] = a2c;
    if (ok3) g_wpart[chunk][base + i3] = a3;
}

// ---------------------------------------------------------
// stage-1 reduce: grid (NB1, 4 segs); per-block partial stats
// ---------------------------------------------------------
__global__ void __launch_bounds__(256)
reduce1_kernel(int N) {
    __shared__ float sh[8][4];
    const float INV2PI = 0.15915494309189535f;
    int seg = blockIdx.y;
    int per = (N + NB1 - 1) / NB1;
    int n0 = blockIdx.x * per;
    int n1 = min(N, n0 + per);
    int tid = threadIdx.x;
    int lane = tid & 31;
    int warp = tid >> 5;

    float mn = BIGF, mx = -BIGF, s = 0.0f, c = 0.0f;
    for (int n = n0 + tid; n < n1; n += 256) {
        int ia = seg * NMAX + n;
        float w = 0.0f, ms = BIGF;
        #pragma unroll
        for (int ch = 0; ch < WCH; ch++) w += g_wpart[ch][ia];
        #pragma unroll
        for (int ch = 0; ch < MCH; ch++) ms = fminf(ms, g_mpart[ch][ia]);
        float rm = sqrtf(fmaxf(ms, 0.0f));
        mn = fminf(mn, rm);
        if (w * INV2PI >= 0.99f) { mx = fmaxf(mx, rm); s += rm; c += 1.0f; }
    }
    #pragma unroll
    for (int o = 16; o; o >>= 1) {
        mn = fminf(mn, __shfl_xor_sync(0xffffffffu, mn, o));
        mx = fmaxf(mx, __shfl_xor_sync(0xffffffffu, mx, o));
        s +=           __shfl_xor_sync(0xffffffffu, s,  o);
        c +=           __shfl_xor_sync(0xffffffffu, c,  o);
    }
    if (lane == 0) { sh[warp][0] = mn; sh[warp][1] = mx; sh[warp][2] = s; sh[warp][3] = c; }
    __syncthreads();
    if (tid == 0) {
        #pragma unroll
        for (int w = 1; w < 8; w++) {
            mn = fminf(mn, sh[w][0]);
            mx = fmaxf(mx, sh[w][1]);
            s += sh[w][2];
            c += sh[w][3];
        }
        g_red[seg][blockIdx.x] = make_float4(mn, mx, s, c);
    }
}

// ---------------------------------------------------------
// stage-2 reduce: 4 warps, one per seg; lanes over NB1 blocks
// out layout: [5][B] row-major
// ---------------------------------------------------------
__global__ void __launch_bounds__(128)
reduce2_kernel(float* __restrict__ out) {
    __shared__ float sh[4][4];
    int tid = threadIdx.x;
    int lane = tid & 31;
    int seg = tid >> 5;

    float4 v = g_red[seg][lane];   // NB1 == 32
    float mn = v.x, mx = v.y, s = v.z, c = v.w;
    #pragma unroll
    for (int o = 16; o; o >>= 1) {
        mn = fminf(mn, __shfl_xor_sync(0xffffffffu, mn, o));
        mx = fmaxf(mx, __shfl_xor_sync(0xffffffffu, mx, o));
        s +=           __shfl_xor_sync(0xffffffffu, s,  o);
        c +=           __shfl_xor_sync(0xffffffffu, c,  o);
    }
    if (lane == 0) { sh[seg][0] = mn; sh[seg][1] = mx; sh[seg][2] = s; sh[seg][3] = c; }
    __syncthreads();
    if (tid < B_) {
        int b = tid;
        float mn0 = sh[b][0];
        float mx1 = sh[b][1], s1 = sh[b][2], c1 = sh[b][3];
        float mx2 = sh[2 + b][1], s2 = sh[2 + b][2], c2 = sh[2 + b][3];
        out[0 * B_ + b] = mn0;
        out[1 * B_ + b] = (c1 > 0.0f) ? mx1 : 0.0f;
        out[2 * B_ + b] = (c1 > 0.0f) ? s1 / fmaxf(c1, 1.0f) : 0.0f;
        out[3 * B_ + b] = (c2 > 0.0f) ? mx2 : 0.0f;
        out[4 * B_ + b] = (c2 > 0.0f) ? s2 / fmaxf(c2, 1.0f) : 0.0f;
    }
}

// ---------------------------------------------------------
extern "C" void kernel_launch(void* const* d_in, const int* in_sizes, int n_in,
                              void* d_out, int out_size) {
    const float* v1 = (const float*)d_in[0];
    const float* v2 = (const float*)d_in[1];
    const int* faces = (const int*)d_in[2];
    float* out = (float*)d_out;

    int N = in_sizes[0] / (3 * B_);   // 6890
    int NF = in_sizes[2] / 3;         // 2000

    // launches 1-2: gather (split so winding is the 4th launch, the ncu slot)
    gather_pts_kernel<<<(B_ * N + 255) / 256, 256>>>(v1, v2, N);
    gather_tri_kernel<<<(B_ * NF + 255) / 256, 256>>>(v1, v2, faces, N, NF);

    // launch 3: minsq (588 blocks)
    int Q = (N + 3) >> 2;
    dim3 mgrid((Q + 255) / 256, 4 * MCH);
    minsq_kernel<<<mgrid, 256>>>(N);

    // launch 4: winding (448 blocks ~ one wave at 3 blocks/SM, law-of-cosines)
    int H4 = (N + 3) >> 2;
    dim3 wgrid((H4 + 255) / 256, 4 * WCH);
    winding_kernel<<<wgrid, 256>>>(N, NF);

    dim3 rgrid(NB1, 4);
    reduce1_kernel<<<rgrid, 256>>>(N);
    reduce2_kernel<<<1, 128>>>(out);
}

// round 16
// speedup vs baseline: 1.0904x; 1.0904x over previous
#include <cuda_runtime.h>
#include <math.h>

// Problem constants (fixed by setup_inputs): B=2, N=6890, NF=2000
#define B_    2
#define NMAX  7168
#define NFMAX 2048
#define WCH   28       // triangle chunks for winding  (7*4*28 = 784 blocks)
#define WFPC  72       // max tris per chunk staged in smem (ceil(2000/28)=72)
#define MCH   21       // point chunks for minsq       (7*4*21 = 588 blocks)
#define NB1   32       // stage-1 reduce blocks per segment
#define NTC   19       // triangle components (law-of-cosines form)
#define BIGF  3.4e38f

typedef unsigned long long ull;

// -------- device scratch (no allocations allowed) --------
__device__ float4 g_pts4[2][B_ * NMAX];            // (x,y,z,|p|^2)
// triangles SoA: [src][ (b*NTC + comp)*NFMAX + f ]
// comps: 0-2 2A, 3 |A|^2, 4-6 2B, 7 |B|^2, 8-10 2C, 11 |C|^2,
//        12-14 n=(B-A)x(C-A), 15 d0=A.n,
//        16 -|A-B|^2, 17 -|B-C|^2, 18 -|C-A|^2
__device__ float g_triS[2][B_ * NTC * NFMAX];
__device__ float g_wpart[WCH][4 * NMAX];           // partial atan2 sums
__device__ float g_mpart[MCH][4 * NMAX];           // partial sq-dist mins
__device__ float4 g_red[4][NB1];                   // (mn, mx, sum, cnt)

// ---------------- packed f32x2 helpers (sm_100+) ----------------
__device__ __forceinline__ ull pk2(float lo, float hi) {
    ull r;
    asm("mov.b64 %0, {%1, %2};" : "=l"(r)
        : "r"(__float_as_uint(lo)), "r"(__float_as_uint(hi)));
    return r;
}
__device__ __forceinline__ float2 unpk2(ull v) {
    unsigned int lo, hi;
    asm("mov.b64 {%0, %1}, %2;" : "=r"(lo), "=r"(hi) : "l"(v));
    return make_float2(__uint_as_float(lo), __uint_as_float(hi));
}
__device__ __forceinline__ ull fma2(ull a, ull b, ull c) {
    ull d; asm("fma.rn.f32x2 %0, %1, %2, %3;" : "=l"(d) : "l"(a), "l"(b), "l"(c)); return d;
}
__device__ __forceinline__ ull add2(ull a, ull b) {
    ull d; asm("add.rn.f32x2 %0, %1, %2;" : "=l"(d) : "l"(a), "l"(b)); return d;
}
__device__ __forceinline__ ull mul2(ull a, ull b) {
    ull d; asm("mul.rn.f32x2 %0, %1, %2;" : "=l"(d) : "l"(a), "l"(b)); return d;
}
__device__ __forceinline__ float sqrt_ap(float x) {
    float r; asm("sqrt.approx.f32 %0, %1;" : "=f"(r) : "f"(x)); return r;
}

// ---------------------------------------------------------
// gather A: float4 points (with |p|^2)
// ---------------------------------------------------------
__global__ void gather_pts_kernel(const float* __restrict__ v1,
                                  const float* __restrict__ v2,
                                  int N) {
    int stride = gridDim.x * blockDim.x;
    int t0 = blockIdx.x * blockDim.x + threadIdx.x;
    int PT = B_ * N;
    for (int i = t0; i < PT; i += stride) {
        float x = v1[i * 3 + 0], y = v1[i * 3 + 1], z = v1[i * 3 + 2];
        g_pts4[0][i] = make_float4(x, y, z, fmaf(x, x, fmaf(y, y, z * z)));
        x = v2[i * 3 + 0]; y = v2[i * 3 + 1]; z = v2[i * 3 + 2];
        g_pts4[1][i] = make_float4(x, y, z, fmaf(x, x, fmaf(y, y, z * z)));
    }
}

// ---------------------------------------------------------
// gather B: triangle SoA (law-of-cosines form)
// ---------------------------------------------------------
__global__ void gather_tri_kernel(const float* __restrict__ v1,
                                  const float* __restrict__ v2,
                                  const int*   __restrict__ faces,
                                  int N, int NF) {
    int stride = gridDim.x * blockDim.x;
    int t0 = blockIdx.x * blockDim.x + threadIdx.x;
    int FT = B_ * NF;
    for (int i = t0; i < FT; i += stride) {
        int b = i / NF;
        int f = i - b * NF;
        int i0 = faces[f * 3 + 0];
        int i1 = faces[f * 3 + 1];
        int i2 = faces[f * 3 + 2];
        int base = b * N * 3;
        #pragma unroll
        for (int s = 0; s < 2; s++) {
            const float* v = (s == 0) ? v1 : v2;
            float Ax = v[base + i0 * 3 + 0], Ay = v[base + i0 * 3 + 1], Az = v[base + i0 * 3 + 2];
            float Bx = v[base + i1 * 3 + 0], By = v[base + i1 * 3 + 1], Bz = v[base + i1 * 3 + 2];
            float Cx = v[base + i2 * 3 + 0], Cy = v[base + i2 * 3 + 1], Cz = v[base + i2 * 3 + 2];
            float ex = Bx - Ax, ey = By - Ay, ez = Bz - Az;
            float fx = Cx - Ax, fy = Cy - Ay, fz = Cz - Az;
            float gx = Cx - Bx, gy = Cy - By, gz = Cz - Bz;
            float nx = fmaf(ey, fz, -ez * fy);
            float ny = fmaf(ez, fx, -ex * fz);
            float nz = fmaf(ex, fy, -ey * fx);
            float d0 = fmaf(Ax, nx, fmaf(Ay, ny, Az * nz));
            float A2 = fmaf(Ax, Ax, fmaf(Ay, Ay, Az * Az));
            float B2 = fmaf(Bx, Bx, fmaf(By, By, Bz * Bz));
            float C2 = fmaf(Cx, Cx, fmaf(Cy, Cy, Cz * Cz));
            float Lab = fmaf(ex, ex, fmaf(ey, ey, ez * ez));   // |A-B|^2
            float Lbc = fmaf(gx, gx, fmaf(gy, gy, gz * gz));   // |B-C|^2
            float Lca = fmaf(fx, fx, fmaf(fy, fy, fz * fz));   // |C-A|^2
            float* T = g_triS[s] + (size_t)(b * NTC) * NFMAX + f;
            T[0 * NFMAX] = 2.0f * Ax;  T[1 * NFMAX] = 2.0f * Ay;  T[2 * NFMAX] = 2.0f * Az;
            T[3 * NFMAX] = A2;
            T[4 * NFMAX] = 2.0f * Bx;  T[5 * NFMAX] = 2.0f * By;  T[6 * NFMAX] = 2.0f * Bz;
            T[7 * NFMAX] = B2;
            T[8 * NFMAX] = 2.0f * Cx;  T[9 * NFMAX] = 2.0f * Cy;  T[10 * NFMAX] = 2.0f * Cz;
            T[11 * NFMAX] = C2;
            T[12 * NFMAX] = nx;  T[13 * NFMAX] = ny;  T[14 * NFMAX] = nz;
            T[15 * NFMAX] = d0;
            T[16 * NFMAX] = -Lab;  T[17 * NFMAX] = -Lbc;  T[18 * NFMAX] = -Lca;
        }
    }
}

// ---------------------------------------------------------
// minsq: 4 scalar points per thread vs packed pairs of q.
// grid: x covers Q=ceil(N/4), y = seg*MCH + chunk (seg = dir*2+b)
// ---------------------------------------------------------
__global__ void __launch_bounds__(256)
minsq_kernel(int N) {
    int yc = blockIdx.y;
    int seg = yc / MCH;
    int chunk = yc - seg * MCH;
    int dir = seg >> 1;
    int b = seg & 1;
    int Q = (N + 3) >> 2;
    int t = blockIdx.x * 256 + threadIdx.x;
    if (t >= Q) return;

    const float4* __restrict__ P = g_pts4[dir] + b * N;
    const float4* __restrict__ O = g_pts4[1 - dir] + b * N;

    int i0 = t, i1 = t + Q, i2 = t + 2 * Q, i3 = t + 3 * Q;
    bool ok3 = (i3 < N);
    float4 p0 = P[i0];
    float4 p1 = P[i1];
    float4 p2 = P[i2];
    float4 p3 = ok3 ? P[i3] : p2;

    ull p0x = pk2(p0.x, p0.x), p0y = pk2(p0.y, p0.y), p0z = pk2(p0.z, p0.z);
    ull p1x = pk2(p1.x, p1.x), p1y = pk2(p1.y, p1.y), p1z = pk2(p1.z, p1.z);
    ull p2x = pk2(p2.x, p2.x), p2y = pk2(p2.y, p2.y), p2z = pk2(p2.z, p2.z);
    ull p3x = pk2(p3.x, p3.x), p3y = pk2(p3.y, p3.y), p3z = pk2(p3.z, p3.z);
    ull m2  = pk2(-2.0f, -2.0f);

    int mpc = (N + MCH - 1) / MCH;
    int m0 = chunk * mpc;
    int m1 = min(N, m0 + mpc);

    float b0 = BIGF, b1v = BIGF, b2v = BIGF, b3v = BIGF;
    int m = m0;
    for (; m + 1 < m1; m += 2) {
        float4 qa = O[m];
        float4 qb = O[m + 1];
        ull qx = pk2(qa.x, qb.x);
        ull qy = pk2(qa.y, qb.y);
        ull qz = pk2(qa.z, qb.z);
        ull qw = pk2(qa.w, qb.w);

        ull d0 = fma2(p0x, qx, fma2(p0y, qy, mul2(p0z, qz)));
        ull d1 = fma2(p1x, qx, fma2(p1y, qy, mul2(p1z, qz)));
        ull d2 = fma2(p2x, qx, fma2(p2y, qy, mul2(p2z, qz)));
        ull d3 = fma2(p3x, qx, fma2(p3y, qy, mul2(p3z, qz)));
        float2 v0 = unpk2(fma2(m2, d0, qw));
        float2 v1 = unpk2(fma2(m2, d1, qw));
        float2 v2 = unpk2(fma2(m2, d2, qw));
        float2 v3 = unpk2(fma2(m2, d3, qw));
        b0  = fminf(b0,  fminf(v0.x, v0.y));
        b1v = fminf(b1v, fminf(v1.x, v1.y));
        b2v = fminf(b2v, fminf(v2.x, v2.y));
        b3v = fminf(b3v, fminf(v3.x, v3.y));
    }
    for (; m < m1; ++m) {
        float4 q = O[m];
        float d0 = fmaf(p0.x, q.x, fmaf(p0.y, q.y, p0.z * q.z));
        float d1 = fmaf(p1.x, q.x, fmaf(p1.y, q.y, p1.z * q.z));
        float d2 = fmaf(p2.x, q.x, fmaf(p2.y, q.y, p2.z * q.z));
        float d3 = fmaf(p3.x, q.x, fmaf(p3.y, q.y, p3.z * q.z));
        b0  = fminf(b0,  fmaf(-2.0f, d0, q.w));
        b1v = fminf(b1v, fmaf(-2.0f, d1, q.w));
        b2v = fminf(b2v, fmaf(-2.0f, d2, q.w));
        b3v = fminf(b3v, fmaf(-2.0f, d3, q.w));
    }
    int base = seg * NMAX;
    g_mpart[chunk][base + i0] = b0 + p0.w;
    g_mpart[chunk][base + i1] = b1v + p1.w;
    g_mpart[chunk][base + i2] = b2v + p2.w;
    if (ok3) g_mpart[chunk][base + i3] = b3v + p3.w;
}

// ---------------------------------------------------------
// packed solid-angle term via law-of-cosines (no diff vectors):
//   a2 = |p|^2 - 2A.p + |A|^2          (np = -p, t2A = 2A)
//   2*a.b = a2 + b2 - |A-B|^2          (s-terms)
//   atan2(2det, 2den) == atan2(det, den)
// ---------------------------------------------------------
__device__ __forceinline__ void pair_accum(
    ull npx, ull npy, ull npz, ull ppw,
    ull t2Ax, ull t2Ay, ull t2Az, ull tA2,
    ull t2Bx, ull t2By, ull t2Bz, ull tB2,
    ull t2Cx, ull t2Cy, ull t2Cz, ull tC2,
    ull tnx, ull tny, ull tnz, ull td0,
    ull tmLab, ull tmLbc, ull tmLca,
    ull C4, ull C3, ull C2c, ull C1, ull C0, ull CC,
    float& acc0, float& acc1)
{
    ull a2 = add2(fma2(t2Ax, npx, fma2(t2Ay, npy, fma2(t2Az, npz, tA2))), ppw);
    ull b2 = add2(fma2(t2Bx, npx, fma2(t2By, npy, fma2(t2Bz, npz, tB2))), ppw);
    ull c2 = add2(fma2(t2Cx, npx, fma2(t2Cy, npy, fma2(t2Cz, npz, tC2))), ppw);

    ull det = fma2(npx, tnx, fma2(npy, tny, fma2(npz, tnz, td0)));

    ull sab = add2(add2(a2, b2), tmLab);   // 2 a.b
    ull sbc = add2(add2(b2, c2), tmLbc);   // 2 b.c
    ull sca = add2(add2(c2, a2), tmLca);   // 2 c.a

    float2 a2s = unpk2(a2), b2s = unpk2(b2), c2s = unpk2(c2);
    ull la = pk2(sqrt_ap(a2s.x), sqrt_ap(a2s.y));
    ull lb = pk2(sqrt_ap(b2s.x), sqrt_ap(b2s.y));
    ull lc = pk2(sqrt_ap(c2s.x), sqrt_ap(c2s.y));

    // den2 = 2*den = (2 la lb + sab) lc + sbc la + sca lb
    ull lb2v = add2(lb, lb);
    ull den = fma2(fma2(la, lb2v, sab), lc,
              fma2(sbc, la, mul2(sca, lb)));
    ull dt2 = add2(det, det);              // 2*det

    // scalar range reduction
    float2 d = unpk2(dt2), n = unpk2(den);
    float ax0 = fabsf(n.x), ay0 = fabsf(d.x);
    float mx0 = fmaxf(ax0, ay0), mn0 = fminf(ax0, ay0);
    float t0 = __fdividef(mn0, fmaxf(mx0, 1e-37f));
    float ax1 = fabsf(n.y), ay1 = fabsf(d.y);
    float mx1 = fmaxf(ax1, ay1), mn1 = fminf(ax1, ay1);
    float t1 = __fdividef(mn1, fmaxf(mx1, 1e-37f));

    // packed polynomial (6-coeff Horner)
    ull T = pk2(t0, t1);
    ull S = mul2(T, T);
    ull Pp = fma2(S, C4, C3);
    Pp = fma2(S, Pp, C2c);
    Pp = fma2(S, Pp, C1);
    Pp = fma2(S, Pp, C0);
    Pp = fma2(S, Pp, CC);
    float2 r = unpk2(mul2(Pp, T));

    // branch-free quadrant fixups + sign via XOR
    {
        bool qhi  = ay0 > ax0;
        bool qneg = n.x < 0.0f;
        float base = qhi ? 1.57079632679f : 0.0f;
        if (qneg) base = 3.14159265359f - base;
        float rs = (qhi != qneg) ? -r.x : r.x;
        float res = base + rs;
        unsigned int sgn = __float_as_uint(d.x) & 0x80000000u;
        acc0 += __uint_as_float(__float_as_uint(res) ^ sgn);
    }
    {
        bool qhi  = ay1 > ax1;
        bool qneg = n.y < 0.0f;
        float base = qhi ? 1.57079632679f : 0.0f;
        if (qneg) base = 3.14159265359f - base;
        float rs = (qhi != qneg) ? -r.y : r.y;
        float res = base + rs;
        unsigned int sgn = __float_as_uint(d.y) & 0x80000000u;
        acc1 += __uint_as_float(__float_as_uint(res) ^ sgn);
    }
}

// ---------------------------------------------------------
// winding: 4 points per thread as two f32x2 pairs; triangle chunk
// staged in smem as duplicated (v,v) pairs (LDS.64 operands).
// grid: x covers H4=ceil(N/4), y = seg*WCH + chunk (seg = dir*2+b)
// ---------------------------------------------------------
__global__ void __launch_bounds__(256)
winding_kernel(int N, int NF) {
    __shared__ ull smT[NTC][WFPC];

    int yc = blockIdx.y;
    int seg = yc / WCH;
    int chunk = yc - seg * WCH;
    int dir = seg >> 1;
    int b = seg & 1;
    int H4 = (N + 3) >> 2;
    int t = blockIdx.x * 256 + threadIdx.x;

    int src = 1 - dir;
    int fpc = (NF + WCH - 1) / WCH;
    int f0 = chunk * fpc;
    int f1 = min(NF, f0 + fpc);
    int nf = f1 - f0;           // <= WFPC

    // cooperative stage: duplicated-pair layout
    {
        const float* Tb = g_triS[src] + (size_t)(b * NTC) * NFMAX + f0;
        #pragma unroll
        for (int c = 0; c < NTC; c++) {
            for (int j = threadIdx.x; j < nf; j += 256) {
                float v = Tb[c * NFMAX + j];
                smT[c][j] = pk2(v, v);
            }
        }
    }
    __syncthreads();

    if (t >= H4) return;

    const float4* __restrict__ P = g_pts4[dir] + b * N;
    int i0 = t, i1 = t + H4, i2 = t + 2 * H4, i3 = t + 3 * H4;
    bool ok3 = (i3 < N);
    float4 p0 = P[i0];
    float4 p1 = P[i1];
    float4 p2 = P[i2];
    float4 p3 = ok3 ? P[i3] : p2;

    ull nAx = pk2(-p0.x, -p1.x), nAy = pk2(-p0.y, -p1.y), nAz = pk2(-p0.z, -p1.z);
    ull nBx = pk2(-p2.x, -p3.x), nBy = pk2(-p2.y, -p3.y), nBz = pk2(-p2.z, -p3.z);
    ull pwA = pk2(p0.w, p1.w);
    ull pwB = pk2(p2.w, p3.w);

    ull C4 = pk2(-0.01172120f, -0.01172120f);
    ull C3 = pk2( 0.05265332f,  0.05265332f);
    ull C2c = pk2(-0.11643287f, -0.11643287f);
    ull C1 = pk2( 0.19354346f,  0.19354346f);
    ull C0 = pk2(-0.33262347f, -0.33262347f);
    ull CC = pk2( 0.99997726f,  0.99997726f);

    float a0 = 0.0f, a1 = 0.0f, a2c = 0.0f, a3 = 0.0f;
    for (int j = 0; j < nf; ++j) {
        ull t2Ax = smT[0][j],  t2Ay = smT[1][j],  t2Az = smT[2][j],  tA2 = smT[3][j];
        ull t2Bx = smT[4][j],  t2By = smT[5][j],  t2Bz = smT[6][j],  tB2 = smT[7][j];
        ull t2Cx = smT[8][j],  t2Cy = smT[9][j],  t2Cz = smT[10][j], tC2 = smT[11][j];
        ull tnx = smT[12][j],  tny = smT[13][j],  tnz = smT[14][j],  td0 = smT[15][j];
        ull tmLab = smT[16][j], tmLbc = smT[17][j], tmLca = smT[18][j];

        pair_accum(nAx, nAy, nAz, pwA,
                   t2Ax, t2Ay, t2Az, tA2, t2Bx, t2By, t2Bz, tB2,
                   t2Cx, t2Cy, t2Cz, tC2, tnx, tny, tnz, td0,
                   tmLab, tmLbc, tmLca,
                   C4, C3, C2c, C1, C0, CC, a0, a1);
        pair_accum(nBx, nBy, nBz, pwB,
                   t2Ax, t2Ay, t2Az, tA2, t2Bx, t2By, t2Bz, tB2,
                   t2Cx, t2Cy, t2Cz, tC2, tnx, tny, tnz, td0,
                   tmLab, tmLbc, tmLca,
                   C4, C3, C2c, C1, C0, CC, a2c, a3);
    }
    int base = seg * NMAX;
    g_wpart[chunk][base + i0] = a0;
    g_wpart[chunk][base + i1] = a1;
    g_wpart[chunk][base + i2] = a2c;
    if (ok3) g_wpart[chunk][base + i3] = a3;
}

// ---------------------------------------------------------
// stage-1 reduce: grid (NB1, 4 segs); per-block partial stats
// ---------------------------------------------------------
__global__ void __launch_bounds__(256)
reduce1_kernel(int N) {
    __shared__ float sh[8][4];
    const float INV2PI = 0.15915494309189535f;
    int seg = blockIdx.y;
    int per = (N + NB1 - 1) / NB1;
    int n0 = blockIdx.x * per;
    int n1 = min(N, n0 + per);
    int tid = threadIdx.x;
    int lane = tid & 31;
    int warp = tid >> 5;

    float mn = BIGF, mx = -BIGF, s = 0.0f, c = 0.0f;
    for (int n = n0 + tid; n < n1; n += 256) {
        int ia = seg * NMAX + n;
        float w = 0.0f, ms = BIGF;
        #pragma unroll
        for (int ch = 0; ch < WCH; ch++) w += g_wpart[ch][ia];
        #pragma unroll
        for (int ch = 0; ch < MCH; ch++) ms = fminf(ms, g_mpart[ch][ia]);
        float rm = sqrtf(fmaxf(ms, 0.0f));
        mn = fminf(mn, rm);
        if (w * INV2PI >= 0.99f) { mx = fmaxf(mx, rm); s += rm; c += 1.0f; }
    }
    #pragma unroll
    for (int o = 16; o; o >>= 1) {
        mn = fminf(mn, __shfl_xor_sync(0xffffffffu, mn, o));
        mx = fmaxf(mx, __shfl_xor_sync(0xffffffffu, mx, o));
        s +=           __shfl_xor_sync(0xffffffffu, s,  o);
        c +=           __shfl_xor_sync(0xffffffffu, c,  o);
    }
    if (lane == 0) { sh[warp][0] = mn; sh[warp][1] = mx; sh[warp][2] = s; sh[warp][3] = c; }
    __syncthreads();
    if (tid == 0) {
        #pragma unroll
        for (int w = 1; w < 8; w++) {
            mn = fminf(mn, sh[w][0]);
            mx = fmaxf(mx, sh[w][1]);
            s += sh[w][2];
            c += sh[w][3];
        }
        g_red[seg][blockIdx.x] = make_float4(mn, mx, s, c);
    }
}

// ---------------------------------------------------------
// stage-2 reduce: 4 warps, one per seg; lanes over NB1 blocks
// out layout: [5][B] row-major
// ---------------------------------------------------------
__global__ void __launch_bounds__(128)
reduce2_kernel(float* __restrict__ out) {
    __shared__ float sh[4][4];
    int tid = threadIdx.x;
    int lane = tid & 31;
    int seg = tid >> 5;

    float4 v = g_red[seg][lane];   // NB1 == 32
    float mn = v.x, mx = v.y, s = v.z, c = v.w;
    #pragma unroll
    for (int o = 16; o; o >>= 1) {
        mn = fminf(mn, __shfl_xor_sync(0xffffffffu, mn, o));
        mx = fmaxf(mx, __shfl_xor_sync(0xffffffffu, mx, o));
        s +=           __shfl_xor_sync(0xffffffffu, s,  o);
        c +=           __shfl_xor_sync(0xffffffffu, c,  o);
    }
    if (lane == 0) { sh[seg][0] = mn; sh[seg][1] = mx; sh[seg][2] = s; sh[seg][3] = c; }
    __syncthreads();
    if (tid < B_) {
        int b = tid;
        float mn0 = sh[b][0];
        float mx1 = sh[b][1], s1 = sh[b][2], c1 = sh[b][3];
        float mx2 = sh[2 + b][1], s2 = sh[2 + b][2], c2 = sh[2 + b][3];
        out[0 * B_ + b] = mn0;
        out[1 * B_ + b] = (c1 > 0.0f) ? mx1 : 0.0f;
        out[2 * B_ + b] = (c1 > 0.0f) ? s1 / fmaxf(c1, 1.0f) : 0.0f;
        out[3 * B_ + b] = (c2 > 0.0f) ? mx2 : 0.0f;
        out[4 * B_ + b] = (c2 > 0.0f) ? s2 / fmaxf(c2, 1.0f) : 0.0f;
    }
}

// ---------------------------------------------------------
extern "C" void kernel_launch(void* const* d_in, const int* in_sizes, int n_in,
                              void* d_out, int out_size) {
    const float* v1 = (const float*)d_in[0];
    const float* v2 = (const float*)d_in[1];
    const int* faces = (const int*)d_in[2];
    float* out = (float*)d_out;

    int N = in_sizes[0] / (3 * B_);   // 6890
    int NF = in_sizes[2] / 3;         // 2000

    // launches 1-2: gather (split so winding is the 4th launch, the ncu slot)
    gather_pts_kernel<<<(B_ * N + 255) / 256, 256>>>(v1, v2, N);
    gather_tri_kernel<<<(B_ * NF + 255) / 256, 256>>>(v1, v2, faces, N, NF);

    // launch 3: minsq (588 blocks)
    int Q = (N + 3) >> 2;
    dim3 mgrid((Q + 255) / 256, 4 * MCH);
    minsq_kernel<<<mgrid, 256>>>(N);

    // launch 4: winding (784 blocks, finer chunks for load balancing)
    int H4 = (N + 3) >> 2;
    dim3 wgrid((H4 + 255) / 256, 4 * WCH);
    winding_kernel<<<wgrid, 256>>>(N, NF);

    dim3 rgrid(NB1, 4);
    reduce1_kernel<<<rgrid, 256>>>(N);
    reduce2_kernel<<<1, 128>>>(out);
}

// round 17
// speedup vs baseline: 1.2050x; 1.1051x over previous
#include <cuda_runtime.h>
#include <math.h>

// Problem constants (fixed by setup_inputs): B=2, N=6890, NF=2000
#define B_    2
#define NMAX  7168
#define HN2   3584     // NMAX/2, packed point-pair stride
#define NFMAX 2048
#define WCH   21       // triangle chunks for winding  (7*4*21 = 588 blocks)
#define WFPC  96       // max tris per chunk staged in smem (ceil(2000/21)=96)
#define MCH   21       // point chunks for minsq       (7*4*21 = 588 blocks)
#define NB1   32       // stage-1 reduce blocks per segment
#define NTC   19       // triangle components (law-of-cosines form)
#define BIGF  3.4e38f

typedef unsigned long long ull;

// -------- device scratch (no allocations allowed) --------
__device__ float4 g_pts4[2][B_ * NMAX];            // (x,y,z,|p|^2)
// packed point pairs: comp c of points (2k,2k+1) in batch b at [c][b*HN2+k]
__device__ ull g_ptsQ[2][4][B_ * HN2];
// triangles SoA: [src][ (b*NTC + comp)*NFMAX + f ]
// comps: 0-2 2A, 3 |A|^2, 4-6 2B, 7 |B|^2, 8-10 2C, 11 |C|^2,
//        12-14 n=(B-A)x(C-A), 15 d0=A.n,
//        16 -|A-B|^2, 17 -|B-C|^2, 18 -|C-A|^2
__device__ float g_triS[2][B_ * NTC * NFMAX];
__device__ float g_wpart[WCH][4 * NMAX];           // partial atan2 sums
__device__ float g_mpart[MCH][4 * NMAX];           // partial sq-dist mins
__device__ float4 g_red[4][NB1];                   // (mn, mx, sum, cnt)

// ---------------- packed f32x2 helpers (sm_100+) ----------------
__device__ __forceinline__ ull pk2(float lo, float hi) {
    ull r;
    asm("mov.b64 %0, {%1, %2};" : "=l"(r)
        : "r"(__float_as_uint(lo)), "r"(__float_as_uint(hi)));
    return r;
}
__device__ __forceinline__ float2 unpk2(ull v) {
    unsigned int lo, hi;
    asm("mov.b64 {%0, %1}, %2;" : "=r"(lo), "=r"(hi) : "l"(v));
    return make_float2(__uint_as_float(lo), __uint_as_float(hi));
}
__device__ __forceinline__ ull fma2(ull a, ull b, ull c) {
    ull d; asm("fma.rn.f32x2 %0, %1, %2, %3;" : "=l"(d) : "l"(a), "l"(b), "l"(c)); return d;
}
__device__ __forceinline__ ull add2(ull a, ull b) {
    ull d; asm("add.rn.f32x2 %0, %1, %2;" : "=l"(d) : "l"(a), "l"(b)); return d;
}
__device__ __forceinline__ ull mul2(ull a, ull b) {
    ull d; asm("mul.rn.f32x2 %0, %1, %2;" : "=l"(d) : "l"(a), "l"(b)); return d;
}
__device__ __forceinline__ float sqrt_ap(float x) {
    float r; asm("sqrt.approx.f32 %0, %1;" : "=f"(r) : "f"(x)); return r;
}

// ---------------------------------------------------------
// gather A: float4 points (with |p|^2) + packed pair arrays
// thread k handles pair (2k, 2k+1) within its batch
// ---------------------------------------------------------
__global__ void gather_pts_kernel(const float* __restrict__ v1,
                                  const float* __restrict__ v2,
                                  int N) {
    int stride = gridDim.x * blockDim.x;
    int t0 = blockIdx.x * blockDim.x + threadIdx.x;
    int HP = (N + 1) >> 1;          // pairs per batch (N even -> N/2)
    int TOT = B_ * HP;
    for (int k = t0; k < TOT; k += stride) {
        int b = k / HP;
        int n = (k - b * HP) * 2;
        int i = b * N + n;
        bool ok1 = (n + 1 < N);
        #pragma unroll
        for (int s = 0; s < 2; s++) {
            const float* v = (s == 0) ? v1 : v2;
            float x0 = v[i * 3 + 0], y0 = v[i * 3 + 1], z0 = v[i * 3 + 2];
            float w0 = fmaf(x0, x0, fmaf(y0, y0, z0 * z0));
            g_pts4[s][i] = make_float4(x0, y0, z0, w0);
            float x1 = x0, y1 = y0, z1 = z0, w1 = w0;
            if (ok1) {
                x1 = v[(i + 1) * 3 + 0]; y1 = v[(i + 1) * 3 + 1]; z1 = v[(i + 1) * 3 + 2];
                w1 = fmaf(x1, x1, fmaf(y1, y1, z1 * z1));
                g_pts4[s][i + 1] = make_float4(x1, y1, z1, w1);
            }
            int kk = b * HN2 + (n >> 1);
            g_ptsQ[s][0][kk] = pk2(x0, x1);
            g_ptsQ[s][1][kk] = pk2(y0, y1);
            g_ptsQ[s][2][kk] = pk2(z0, z1);
            g_ptsQ[s][3][kk] = pk2(w0, w1);
        }
    }
}

// ---------------------------------------------------------
// gather B: triangle SoA (law-of-cosines form)
// ---------------------------------------------------------
__global__ void gather_tri_kernel(const float* __restrict__ v1,
                                  const float* __restrict__ v2,
                                  const int*   __restrict__ faces,
                                  int N, int NF) {
    int stride = gridDim.x * blockDim.x;
    int t0 = blockIdx.x * blockDim.x + threadIdx.x;
    int FT = B_ * NF;
    for (int i = t0; i < FT; i += stride) {
        int b = i / NF;
        int f = i - b * NF;
        int i0 = faces[f * 3 + 0];
        int i1 = faces[f * 3 + 1];
        int i2 = faces[f * 3 + 2];
        int base = b * N * 3;
        #pragma unroll
        for (int s = 0; s < 2; s++) {
            const float* v = (s == 0) ? v1 : v2;
            float Ax = v[base + i0 * 3 + 0], Ay = v[base + i0 * 3 + 1], Az = v[base + i0 * 3 + 2];
            float Bx = v[base + i1 * 3 + 0], By = v[base + i1 * 3 + 1], Bz = v[base + i1 * 3 + 2];
            float Cx = v[base + i2 * 3 + 0], Cy = v[base + i2 * 3 + 1], Cz = v[base + i2 * 3 + 2];
            float ex = Bx - Ax, ey = By - Ay, ez = Bz - Az;
            float fx = Cx - Ax, fy = Cy - Ay, fz = Cz - Az;
            float gx = Cx - Bx, gy = Cy - By, gz = Cz - Bz;
            float nx = fmaf(ey, fz, -ez * fy);
            float ny = fmaf(ez, fx, -ex * fz);
            float nz = fmaf(ex, fy, -ey * fx);
            float d0 = fmaf(Ax, nx, fmaf(Ay, ny, Az * nz));
            float A2 = fmaf(Ax, Ax, fmaf(Ay, Ay, Az * Az));
            float B2 = fmaf(Bx, Bx, fmaf(By, By, Bz * Bz));
            float C2 = fmaf(Cx, Cx, fmaf(Cy, Cy, Cz * Cz));
            float Lab = fmaf(ex, ex, fmaf(ey, ey, ez * ez));   // |A-B|^2
            float Lbc = fmaf(gx, gx, fmaf(gy, gy, gz * gz));   // |B-C|^2
            float Lca = fmaf(fx, fx, fmaf(fy, fy, fz * fz));   // |C-A|^2
            float* T = g_triS[s] + (size_t)(b * NTC) * NFMAX + f;
            T[0 * NFMAX] = 2.0f * Ax;  T[1 * NFMAX] = 2.0f * Ay;  T[2 * NFMAX] = 2.0f * Az;
            T[3 * NFMAX] = A2;
            T[4 * NFMAX] = 2.0f * Bx;  T[5 * NFMAX] = 2.0f * By;  T[6 * NFMAX] = 2.0f * Bz;
            T[7 * NFMAX] = B2;
            T[8 * NFMAX] = 2.0f * Cx;  T[9 * NFMAX] = 2.0f * Cy;  T[10 * NFMAX] = 2.0f * Cz;
            T[11 * NFMAX] = C2;
            T[12 * NFMAX] = nx;  T[13 * NFMAX] = ny;  T[14 * NFMAX] = nz;
            T[15 * NFMAX] = d0;
            T[16 * NFMAX] = -Lab;  T[17 * NFMAX] = -Lbc;  T[18 * NFMAX] = -Lca;
        }
    }
}

// ---------------------------------------------------------
// minsq: 4 scalar points per thread vs pre-packed pairs of q.
// grid: x covers Q=ceil(N/4), y = seg*MCH + chunk (seg = dir*2+b)
// Chunk boundaries are even so packed pairs never straddle chunks.
// ---------------------------------------------------------
__global__ void __launch_bounds__(256)
minsq_kernel(int N) {
    int yc = blockIdx.y;
    int seg = yc / MCH;
    int chunk = yc - seg * MCH;
    int dir = seg >> 1;
    int b = seg & 1;
    int Q = (N + 3) >> 2;
    int t = blockIdx.x * 256 + threadIdx.x;
    if (t >= Q) return;

    const float4* __restrict__ P = g_pts4[dir] + b * N;
    const float4* __restrict__ O = g_pts4[1 - dir] + b * N;
    int oth = 1 - dir;
    const ull* __restrict__ QX = g_ptsQ[oth][0] + b * HN2;
    const ull* __restrict__ QY = g_ptsQ[oth][1] + b * HN2;
    const ull* __restrict__ QZ = g_ptsQ[oth][2] + b * HN2;
    const ull* __restrict__ QW = g_ptsQ[oth][3] + b * HN2;

    int i0 = t, i1 = t + Q, i2 = t + 2 * Q, i3 = t + 3 * Q;
    bool ok3 = (i3 < N);
    float4 p0 = P[i0];
    float4 p1 = P[i1];
    float4 p2 = P[i2];
    float4 p3 = ok3 ? P[i3] : p2;

    ull p0x = pk2(p0.x, p0.x), p0y = pk2(p0.y, p0.y), p0z = pk2(p0.z, p0.z);
    ull p1x = pk2(p1.x, p1.x), p1y = pk2(p1.y, p1.y), p1z = pk2(p1.z, p1.z);
    ull p2x = pk2(p2.x, p2.x), p2y = pk2(p2.y, p2.y), p2z = pk2(p2.z, p2.z);
    ull p3x = pk2(p3.x, p3.x), p3y = pk2(p3.y, p3.y), p3z = pk2(p3.z, p3.z);
    ull m2  = pk2(-2.0f, -2.0f);

    // even-aligned chunk bounds
    int mpc = (N + MCH - 1) / MCH;
    mpc = (mpc + 1) & ~1;
    int m0 = chunk * mpc;
    int m1 = min(N, m0 + mpc);
    if (m0 >= m1 && m0 >= N) {
        // empty chunk (can happen with rounded mpc): store BIG
        int base = seg * NMAX;
        g_mpart[chunk][base + i0] = BIGF;
        g_mpart[chunk][base + i1] = BIGF;
        g_mpart[chunk][base + i2] = BIGF;
        if (ok3) g_mpart[chunk][base + i3] = BIGF;
        return;
    }

    float b0 = BIGF, b1v = BIGF, b2v = BIGF, b3v = BIGF;
    int m = m0;
    int k = m0 >> 1;
    for (; m + 1 < m1; m += 2, ++k) {
        ull qx = QX[k];
        ull qy = QY[k];
        ull qz = QZ[k];
        ull qw = QW[k];

        ull d0 = fma2(p0x, qx, fma2(p0y, qy, mul2(p0z, qz)));
        ull d1 = fma2(p1x, qx, fma2(p1y, qy, mul2(p1z, qz)));
        ull d2 = fma2(p2x, qx, fma2(p2y, qy, mul2(p2z, qz)));
        ull d3 = fma2(p3x, qx, fma2(p3y, qy, mul2(p3z, qz)));
        float2 v0 = unpk2(fma2(m2, d0, qw));
        float2 v1 = unpk2(fma2(m2, d1, qw));
        float2 v2 = unpk2(fma2(m2, d2, qw));
        float2 v3 = unpk2(fma2(m2, d3, qw));
        b0  = fminf(b0,  fminf(v0.x, v0.y));
        b1v = fminf(b1v, fminf(v1.x, v1.y));
        b2v = fminf(b2v, fminf(v2.x, v2.y));
        b3v = fminf(b3v, fminf(v3.x, v3.y));
    }
    for (; m < m1; ++m) {
        float4 q = O[m];
        float d0 = fmaf(p0.x, q.x, fmaf(p0.y, q.y, p0.z * q.z));
        float d1 = fmaf(p1.x, q.x, fmaf(p1.y, q.y, p1.z * q.z));
        float d2 = fmaf(p2.x, q.x, fmaf(p2.y, q.y, p2.z * q.z));
        float d3 = fmaf(p3.x, q.x, fmaf(p3.y, q.y, p3.z * q.z));
        b0  = fminf(b0,  fmaf(-2.0f, d0, q.w));
        b1v = fminf(b1v, fmaf(-2.0f, d1, q.w));
        b2v = fminf(b2v, fmaf(-2.0f, d2, q.w));
        b3v = fminf(b3v, fmaf(-2.0f, d3, q.w));
    }
    int base = seg * NMAX;
    g_mpart[chunk][base + i0] = b0 + p0.w;
    g_mpart[chunk][base + i1] = b1v + p1.w;
    g_mpart[chunk][base + i2] = b2v + p2.w;
    if (ok3) g_mpart[chunk][base + i3] = b3v + p3.w;
}

// ---------------------------------------------------------
// packed solid-angle term via law-of-cosines (no diff vectors):
//   a2 = |p|^2 - 2A.p + |A|^2          (np = -p, t2A = 2A)
//   2*a.b = a2 + b2 - |A-B|^2          (s-terms)
//   atan2(2det, 2den) == atan2(det, den)
// ---------------------------------------------------------
__device__ __forceinline__ void pair_accum(
    ull npx, ull npy, ull npz, ull ppw,
    ull t2Ax, ull t2Ay, ull t2Az, ull tA2,
    ull t2Bx, ull t2By, ull t2Bz, ull tB2,
    ull t2Cx, ull t2Cy, ull t2Cz, ull tC2,
    ull tnx, ull tny, ull tnz, ull td0,
    ull tmLab, ull tmLbc, ull tmLca,
    ull C4, ull C3, ull C2c, ull C1, ull C0, ull CC,
    float& acc0, float& acc1)
{
    ull a2 = add2(fma2(t2Ax, npx, fma2(t2Ay, npy, fma2(t2Az, npz, tA2))), ppw);
    ull b2 = add2(fma2(t2Bx, npx, fma2(t2By, npy, fma2(t2Bz, npz, tB2))), ppw);
    ull c2 = add2(fma2(t2Cx, npx, fma2(t2Cy, npy, fma2(t2Cz, npz, tC2))), ppw);

    ull det = fma2(npx, tnx, fma2(npy, tny, fma2(npz, tnz, td0)));

    ull sab = add2(add2(a2, b2), tmLab);   // 2 a.b
    ull sbc = add2(add2(b2, c2), tmLbc);   // 2 b.c
    ull sca = add2(add2(c2, a2), tmLca);   // 2 c.a

    float2 a2s = unpk2(a2), b2s = unpk2(b2), c2s = unpk2(c2);
    ull la = pk2(sqrt_ap(a2s.x), sqrt_ap(a2s.y));
    ull lb = pk2(sqrt_ap(b2s.x), sqrt_ap(b2s.y));
    ull lc = pk2(sqrt_ap(c2s.x), sqrt_ap(c2s.y));

    // den2 = 2*den = (2 la lb + sab) lc + sbc la + sca lb
    ull lb2v = add2(lb, lb);
    ull den = fma2(fma2(la, lb2v, sab), lc,
              fma2(sbc, la, mul2(sca, lb)));
    ull dt2 = add2(det, det);              // 2*det

    // scalar range reduction
    float2 d = unpk2(dt2), n = unpk2(den);
    float ax0 = fabsf(n.x), ay0 = fabsf(d.x);
    float mx0 = fmaxf(ax0, ay0), mn0 = fminf(ax0, ay0);
    float t0 = __fdividef(mn0, fmaxf(mx0, 1e-37f));
    float ax1 = fabsf(n.y), ay1 = fabsf(d.y);
    float mx1 = fmaxf(ax1, ay1), mn1 = fminf(ax1, ay1);
    float t1 = __fdividef(mn1, fmaxf(mx1, 1e-37f));

    // packed polynomial (6-coeff Horner)
    ull T = pk2(t0, t1);
    ull S = mul2(T, T);
    ull Pp = fma2(S, C4, C3);
    Pp = fma2(S, Pp, C2c);
    Pp = fma2(S, Pp, C1);
    Pp = fma2(S, Pp, C0);
    Pp = fma2(S, Pp, CC);
    float2 r = unpk2(mul2(Pp, T));

    // branch-free quadrant fixups + sign via XOR
    {
        bool qhi  = ay0 > ax0;
        bool qneg = n.x < 0.0f;
        float base = qhi ? 1.57079632679f : 0.0f;
        if (qneg) base = 3.14159265359f - base;
        float rs = (qhi != qneg) ? -r.x : r.x;
        float res = base + rs;
        unsigned int sgn = __float_as_uint(d.x) & 0x80000000u;
        acc0 += __uint_as_float(__float_as_uint(res) ^ sgn);
    }
    {
        bool qhi  = ay1 > ax1;
        bool qneg = n.y < 0.0f;
        float base = qhi ? 1.57079632679f : 0.0f;
        if (qneg) base = 3.14159265359f - base;
        float rs = (qhi != qneg) ? -r.y : r.y;
        float res = base + rs;
        unsigned int sgn = __float_as_uint(d.y) & 0x80000000u;
        acc1 += __uint_as_float(__float_as_uint(res) ^ sgn);
    }
}

// ---------------------------------------------------------
// winding: 4 points per thread as two f32x2 pairs; triangle chunk
// staged in smem as duplicated (v,v) pairs (LDS.64 operands).
// grid: x covers H4=ceil(N/4), y = seg*WCH + chunk (seg = dir*2+b)
// ---------------------------------------------------------
__global__ void __launch_bounds__(256)
winding_kernel(int N, int NF) {
    __shared__ ull smT[NTC][WFPC];

    int yc = blockIdx.y;
    int seg = yc / WCH;
    int chunk = yc - seg * WCH;
    int dir = seg >> 1;
    int b = seg & 1;
    int H4 = (N + 3) >> 2;
    int t = blockIdx.x * 256 + threadIdx.x;

    int src = 1 - dir;
    int fpc = (NF + WCH - 1) / WCH;
    int f0 = chunk * fpc;
    int f1 = min(NF, f0 + fpc);
    int nf = f1 - f0;           // <= WFPC

    // cooperative stage: duplicated-pair layout
    {
        const float* Tb = g_triS[src] + (size_t)(b * NTC) * NFMAX + f0;
        #pragma unroll
        for (int c = 0; c < NTC; c++) {
            for (int j = threadIdx.x; j < nf; j += 256) {
                float v = Tb[c * NFMAX + j];
                smT[c][j] = pk2(v, v);
            }
        }
    }
    __syncthreads();

    if (t >= H4) return;

    const float4* __restrict__ P = g_pts4[dir] + b * N;
    int i0 = t, i1 = t + H4, i2 = t + 2 * H4, i3 = t + 3 * H4;
    bool ok3 = (i3 < N);
    float4 p0 = P[i0];
    float4 p1 = P[i1];
    float4 p2 = P[i2];
    float4 p3 = ok3 ? P[i3] : p2;

    ull nAx = pk2(-p0.x, -p1.x), nAy = pk2(-p0.y, -p1.y), nAz = pk2(-p0.z, -p1.z);
    ull nBx = pk2(-p2.x, -p3.x), nBy = pk2(-p2.y, -p3.y), nBz = pk2(-p2.z, -p3.z);
    ull pwA = pk2(p0.w, p1.w);
    ull pwB = pk2(p2.w, p3.w);

    ull C4 = pk2(-0.01172120f, -0.01172120f);
    ull C3 = pk2( 0.05265332f,  0.05265332f);
    ull C2c = pk2(-0.11643287f, -0.11643287f);
    ull C1 = pk2( 0.19354346f,  0.19354346f);
    ull C0 = pk2(-0.33262347f, -0.33262347f);
    ull CC = pk2( 0.99997726f,  0.99997726f);

    float a0 = 0.0f, a1 = 0.0f, a2c = 0.0f, a3 = 0.0f;
    for (int j = 0; j < nf; ++j) {
        ull t2Ax = smT[0][j],  t2Ay = smT[1][j],  t2Az = smT[2][j],  tA2 = smT[3][j];
        ull t2Bx = smT[4][j],  t2By = smT[5][j],  t2Bz = smT[6][j],  tB2 = smT[7][j];
        ull t2Cx = smT[8][j],  t2Cy = smT[9][j],  t2Cz = smT[10][j], tC2 = smT[11][j];
        ull tnx = smT[12][j],  tny = smT[13][j],  tnz = smT[14][j],  td0 = smT[15][j];
        ull tmLab = smT[16][j], tmLbc = smT[17][j], tmLca = smT[18][j];

        pair_accum(nAx, nAy, nAz, pwA,
                   t2Ax, t2Ay, t2Az, tA2, t2Bx, t2By, t2Bz, tB2,
                   t2Cx, t2Cy, t2Cz, tC2, tnx, tny, tnz, td0,
                   tmLab, tmLbc, tmLca,
                   C4, C3, C2c, C1, C0, CC, a0, a1);
        pair_accum(nBx, nBy, nBz, pwB,
                   t2Ax, t2Ay, t2Az, tA2, t2Bx, t2By, t2Bz, tB2,
                   t2Cx, t2Cy, t2Cz, tC2, tnx, tny, tnz, td0,
                   tmLab, tmLbc, tmLca,
                   C4, C3, C2c, C1, C0, CC, a2c, a3);
    }
    int base = seg * NMAX;
    g_wpart[chunk][base + i0] = a0;
    g_wpart[chunk][base + i1] = a1;
    g_wpart[chunk][base + i2] = a2c;
    if (ok3) g_wpart[chunk][base + i3] = a3;
}

// ---------------------------------------------------------
// stage-1 reduce: grid (NB1, 4 segs); per-block partial stats
// ---------------------------------------------------------
__global__ void __launch_bounds__(256)
reduce1_kernel(int N) {
    __shared__ float sh[8][4];
    const float INV2PI = 0.15915494309189535f;
    int seg = blockIdx.y;
    int per = (N + NB1 - 1) / NB1;
    int n0 = blockIdx.x * per;
    int n1 = min(N, n0 + per);
    int tid = threadIdx.x;
    int lane = tid & 31;
    int warp = tid >> 5;

    float mn = BIGF, mx = -BIGF, s = 0.0f, c = 0.0f;
    for (int n = n0 + tid; n < n1; n += 256) {
        int ia = seg * NMAX + n;
        float w = 0.0f, ms = BIGF;
        #pragma unroll
        for (int ch = 0; ch < WCH; ch++) w += g_wpart[ch][ia];
        #pragma unroll
        for (int ch = 0; ch < MCH; ch++) ms = fminf(ms, g_mpart[ch][ia]);
        float rm = sqrtf(fmaxf(ms, 0.0f));
        mn = fminf(mn, rm);
        if (w * INV2PI >= 0.99f) { mx = fmaxf(mx, rm); s += rm; c += 1.0f; }
    }
    #pragma unroll
    for (int o = 16; o; o >>= 1) {
        mn = fminf(mn, __shfl_xor_sync(0xffffffffu, mn, o));
        mx = fmaxf(mx, __shfl_xor_sync(0xffffffffu, mx, o));
        s +=           __shfl_xor_sync(0xffffffffu, s,  o);
        c +=           __shfl_xor_sync(0xffffffffu, c,  o);
    }
    if (lane == 0) { sh[warp][0] = mn; sh[warp][1] = mx; sh[warp][2] = s; sh[warp][3] = c; }
    __syncthreads();
    if (tid == 0) {
        #pragma unroll
        for (int w = 1; w < 8; w++) {
            mn = fminf(mn, sh[w][0]);
            mx = fmaxf(mx, sh[w][1]);
            s += sh[w][2];
            c += sh[w][3];
        }
        g_red[seg][blockIdx.x] = make_float4(mn, mx, s, c);
    }
}

// ---------------------------------------------------------
// stage-2 reduce: 4 warps, one per seg; lanes over NB1 blocks
// out layout: [5][B] row-major
// ---------------------------------------------------------
__global__ void __launch_bounds__(128)
reduce2_kernel(float* __restrict__ out) {
    __shared__ float sh[4][4];
    int tid = threadIdx.x;
    int lane = tid & 31;
    int seg = tid >> 5;

    float4 v = g_red[seg][lane];   // NB1 == 32
    float mn = v.x, mx = v.y, s = v.z, c = v.w;
    #pragma unroll
    for (int o = 16; o; o >>= 1) {
        mn = fminf(mn, __shfl_xor_sync(0xffffffffu, mn, o));
        mx = fmaxf(mx, __shfl_xor_sync(0xffffffffu, mx, o));
        s +=           __shfl_xor_sync(0xffffffffu, s,  o);
        c +=           __shfl_xor_sync(0xffffffffu, c,  o);
    }
    if (lane == 0) { sh[seg][0] = mn; sh[seg][1] = mx; sh[seg][2] = s; sh[seg][3] = c; }
    __syncthreads();
    if (tid < B_) {
        int b = tid;
        float mn0 = sh[b][0];
        float mx1 = sh[b][1], s1 = sh[b][2], c1 = sh[b][3];
        float mx2 = sh[2 + b][1], s2 = sh[2 + b][2], c2 = sh[2 + b][3];
        out[0 * B_ + b] = mn0;
        out[1 * B_ + b] = (c1 > 0.0f) ? mx1 : 0.0f;
        out[2 * B_ + b] = (c1 > 0.0f) ? s1 / fmaxf(c1, 1.0f) : 0.0f;
        out[3 * B_ + b] = (c2 > 0.0f) ? mx2 : 0.0f;
        out[4 * B_ + b] = (c2 > 0.0f) ? s2 / fmaxf(c2, 1.0f) : 0.0f;
    }
}

// ---------------------------------------------------------
extern "C" void kernel_launch(void* const* d_in, const int* in_sizes, int n_in,
                              void* d_out, int out_size) {
    const float* v1 = (const float*)d_in[0];
    const float* v2 = (const float*)d_in[1];
    const int* faces = (const int*)d_in[2];
    float* out = (float*)d_out;

    int N = in_sizes[0] / (3 * B_);   // 6890
    int NF = in_sizes[2] / 3;         // 2000

    // launches 1-2: gather (split so winding is the 4th launch, the ncu slot)
    int HP = B_ * ((N + 1) >> 1);
    gather_pts_kernel<<<(HP + 255) / 256, 256>>>(v1, v2, N);
    gather_tri_kernel<<<(B_ * NF + 255) / 256, 256>>>(v1, v2, faces, N, NF);

    // launch 3: minsq (588 blocks, pre-packed q operands)
    int Q = (N + 3) >> 2;
    dim3 mgrid((Q + 255) / 256, 4 * MCH);
    minsq_kernel<<<mgrid, 256>>>(N);

    // launch 4: winding (588 blocks, champion R13 config)
    int H4 = (N + 3) >> 2;
    dim3 wgrid((H4 + 255) / 256, 4 * WCH);
    winding_kernel<<<wgrid, 256>>>(N, NF);

    dim3 rgrid(NB1, 4);
    reduce1_kernel<<<rgrid, 256>>>(N);
    reduce2_kernel<<<1, 128>>>(out);
}